// round 3
// baseline (speedup 1.0000x reference)
#include <cuda_runtime.h>
#include <math.h>
#include <stdint.h>

// Problem dims (fixed)
#define BB   8
#define TT   4096
#define DD   512
#define HH   512
#define MM   (BB*TT)          // 32768 rows
#define NN   (2*HH)           // 1024 gemm cols
#define KK   DD               // 512

// Chunked scan config
#define CNK  64               // chunks along T
#define CL   (TT/CNK)         // 64 steps per chunk
#define NSEQ (BB*HH)          // 4096 sequences

// ---------------- scratch (device globals: allocation-free) ----------------
__device__ float g_xn[(size_t)MM * DD];        // 64 MB  layernormed x
__device__ float g_gh[(size_t)MM * NN];        // 128 MB gemm output (k | hp)
__device__ float g_c [(size_t)MM * HH];        // 64 MB  per-step coeff
__device__ float g_v [(size_t)MM * HH];        // 64 MB  per-step value
__device__ float g_A [CNK * NSEQ];             // chunk composed A
__device__ float g_Bc[CNK * NSEQ];             // chunk composed B
__device__ float g_P [CNK * NSEQ];             // chunk prefix state

// ---------------- 1. LayerNorm ----------------
__global__ void __launch_bounds__(128) ln_kernel(const float* __restrict__ x,
                                                 const float* __restrict__ gamma,
                                                 const float* __restrict__ beta) {
    const int row = blockIdx.x;
    const int tid = threadIdx.x;               // 128 threads, 4 floats each
    const float4* xr = (const float4*)(x + (size_t)row * DD);
    float4 v = xr[tid];
    float s  = v.x + v.y + v.z + v.w;
    float ss = v.x*v.x + v.y*v.y + v.z*v.z + v.w*v.w;
    #pragma unroll
    for (int o = 16; o; o >>= 1) {
        s  += __shfl_xor_sync(0xffffffffu, s,  o);
        ss += __shfl_xor_sync(0xffffffffu, ss, o);
    }
    __shared__ float sh[8];
    const int w = tid >> 5, l = tid & 31;
    if (l == 0) { sh[w] = s; sh[4 + w] = ss; }
    __syncthreads();
    if (tid == 0) {
        float S  = sh[0] + sh[1] + sh[2] + sh[3];
        float SS = sh[4] + sh[5] + sh[6] + sh[7];
        float mu  = S * (1.0f / DD);
        float var = SS * (1.0f / DD) - mu * mu;
        sh[0] = mu;
        sh[1] = rsqrtf(var + 1e-10f);
    }
    __syncthreads();
    const float mu = sh[0], rs = sh[1];
    float4 g  = ((const float4*)gamma)[tid];
    float4 bb = ((const float4*)beta)[tid];
    float4 o;
    o.x = (v.x - mu) * rs * g.x + bb.x;
    o.y = (v.y - mu) * rs * g.y + bb.y;
    o.z = (v.z - mu) * rs * g.z + bb.z;
    o.w = (v.w - mu) * rs * g.w + bb.w;
    ((float4*)(g_xn + (size_t)row * DD))[tid] = o;
}

// ---------------- 2. GEMM: g_gh = g_xn @ W  (fp32 SIMT 128x128x16) ----------------
#define BM 128
#define BN 128
#define BK 16
#define TM 8
#define TN 8

__global__ void __launch_bounds__(256) gemm_kernel(const float* __restrict__ W) {
    __shared__ float As[BK][BM + 1];   // +1 pad: conflict-free transposed store
    __shared__ float Bs[BK][BN];

    const int tid  = threadIdx.x;
    const int cRow = blockIdx.y;       // 0..255
    const int cCol = blockIdx.x;       // 0..7

    const float* A  = g_xn + (size_t)cRow * BM * KK;
    const float* Bp = W + (size_t)cCol * BN;
    float*       Cp = g_gh + (size_t)cRow * BM * NN + (size_t)cCol * BN;

    const int aRow = tid >> 2;           // 0..63
    const int aCol = (tid & 3) << 2;     // 0,4,8,12
    const int bRow = tid >> 5;           // 0..7
    const int bCol = (tid & 31) << 2;    // 0..124

    const int tr = (tid >> 4) * TM;      // 0..120
    const int tc = (tid & 15) * TN;      // 0..120

    float acc[TM][TN] = {};
    float ra[TM], rb[TN];

    for (int k0 = 0; k0 < KK; k0 += BK) {
        #pragma unroll
        for (int r = 0; r < 2; r++) {
            float4 t = *(const float4*)(A + (size_t)(aRow + r * 64) * KK + k0 + aCol);
            As[aCol + 0][aRow + r * 64] = t.x;
            As[aCol + 1][aRow + r * 64] = t.y;
            As[aCol + 2][aRow + r * 64] = t.z;
            As[aCol + 3][aRow + r * 64] = t.w;
        }
        #pragma unroll
        for (int r = 0; r < 2; r++) {
            *(float4*)&Bs[bRow + r * 8][bCol] =
                *(const float4*)(Bp + (size_t)(k0 + bRow + r * 8) * NN + bCol);
        }
        __syncthreads();
        #pragma unroll
        for (int k = 0; k < BK; k++) {
            #pragma unroll
            for (int i = 0; i < TM; i++) ra[i] = As[k][tr + i];
            #pragma unroll
            for (int j = 0; j < TN; j++) rb[j] = Bs[k][tc + j];
            #pragma unroll
            for (int i = 0; i < TM; i++)
                #pragma unroll
                for (int j = 0; j < TN; j++)
                    acc[i][j] = fmaf(ra[i], rb[j], acc[i][j]);
        }
        __syncthreads();
    }
    #pragma unroll
    for (int i = 0; i < TM; i++) {
        #pragma unroll
        for (int j = 0; j < TN; j += 4) {
            float4 t = { acc[i][j], acc[i][j+1], acc[i][j+2], acc[i][j+3] };
            *(float4*)(Cp + (size_t)(tr + i) * NN + tc + j) = t;
        }
    }
}

// ---------------- 3. Activation: k,hp -> c,v (linear-domain recurrence params) ----
// c = sigmoid(-k);  v = sigmoid(k) * g(hp);  g(hp) = hp>=0 ? hp+0.5 : sigmoid(hp)
__global__ void __launch_bounds__(256) act_kernel() {
    const int idx = blockIdx.x * 256 + threadIdx.x;    // < MM*HH
    const int m = idx >> 9;
    const int h = idx & 511;
    float k  = g_gh[(size_t)m * NN + h];
    float hp = g_gh[(size_t)m * NN + h + HH];
    k = fminf(fmaxf(k, -30.0f), 30.0f);
    float ek = __expf(k);
    float c  = 1.0f / (1.0f + ek);     // sigmoid(-k)
    float z  = ek * c;                 // sigmoid(k), accurate for all k
    float g  = (hp >= 0.0f) ? (hp + 0.5f)
                            : (1.0f / (1.0f + __expf(-hp)));
    g_c[idx] = c;
    g_v[idx] = z * g;
}

// ---------------- 4. Scan phase 1: per-chunk composition ----------------
__global__ void __launch_bounds__(256) scan1_kernel() {
    const int idx = blockIdx.x * 256 + threadIdx.x;    // < NSEQ*CNK
    const int h  = idx & 511;
    const int ci = (idx >> 9) & (CNK - 1);
    const int b  = idx >> 15;
    const int seq = b * HH + h;
    size_t off = ((size_t)(b * TT + ci * CL)) * HH + h;
    float A = 1.0f, Bv = 0.0f;
    #pragma unroll 4
    for (int l = 0; l < CL; l++) {
        float c = g_c[off], v = g_v[off];
        A *= c;
        Bv = fmaf(c, Bv, v);
        off += HH;
    }
    g_A [ci * NSEQ + seq] = A;
    g_Bc[ci * NSEQ + seq] = Bv;
}

// ---------------- 5. Scan phase 2: exclusive scan over chunk ops + hidden ----------
__global__ void __launch_bounds__(256) scan2_kernel(float* __restrict__ hidden) {
    const int seq = blockIdx.x * 256 + threadIdx.x;    // < NSEQ
    float p = 0.0f;
    #pragma unroll 8
    for (int ci = 0; ci < CNK; ci++) {
        g_P[ci * NSEQ + seq] = p;
        p = fmaf(g_A[ci * NSEQ + seq], p, g_Bc[ci * NSEQ + seq]);
    }
    hidden[seq] = p;   // h at t = T-1
}

// ---------------- 6. Scan phase 3: apply prefix, write out = h + x ----------------
__global__ void __launch_bounds__(256) scan3_kernel(const float* __restrict__ x,
                                                    float* __restrict__ out) {
    const int idx = blockIdx.x * 256 + threadIdx.x;
    const int h  = idx & 511;
    const int ci = (idx >> 9) & (CNK - 1);
    const int b  = idx >> 15;
    const int seq = b * HH + h;
    float hs = g_P[ci * NSEQ + seq];
    size_t off = ((size_t)(b * TT + ci * CL)) * HH + h;
    #pragma unroll 4
    for (int l = 0; l < CL; l++) {
        float c = g_c[off], v = g_v[off];
        hs = fmaf(c, hs, v);
        out[off] = hs + x[off];
        off += HH;
    }
}

// ---------------- launch ----------------
extern "C" void kernel_launch(void* const* d_in, const int* in_sizes, int n_in,
                              void* d_out, int out_size) {
    const float* x     = (const float*)d_in[0];
    const float* gamma = (const float*)d_in[1];
    const float* beta  = (const float*)d_in[2];
    const float* W     = (const float*)d_in[3];
    float* out    = (float*)d_out;
    float* hidden = out + (size_t)MM * DD;

    ln_kernel  <<<MM, 128>>>(x, gamma, beta);
    gemm_kernel<<<dim3(NN / BN, MM / BM), 256>>>(W);
    act_kernel <<<(MM * HH) / 256, 256>>>();
    scan1_kernel<<<(NSEQ * CNK) / 256, 256>>>();
    scan2_kernel<<<NSEQ / 256, 256>>>(hidden);
    scan3_kernel<<<(NSEQ * CNK) / 256, 256>>>(x, out);
}

// round 5
// speedup vs baseline: 2.4718x; 2.4718x over previous
#include <cuda_runtime.h>
#include <math.h>
#include <stdint.h>

// Problem dims (fixed)
#define BB   8
#define TT   4096
#define DD   512
#define HH   512
#define MM   (BB*TT)          // 32768 rows
#define NN   (2*HH)           // 1024 gemm cols
#define KK   DD               // 512

// Chunked scan config
#define CNK  64
#define CL   (TT/CNK)         // 64
#define NSEQ (BB*HH)          // 4096

// ---------------- scratch ----------------
__device__ float g_xn[(size_t)MM * DD];        // 64 MB  layernormed x (tf32-rounded)
__device__ float g_Wt[(size_t)NN * KK];        // 2 MB   W transposed + interleaved (tf32-rounded)
__device__ float g_c [(size_t)MM * HH];        // 64 MB
__device__ float g_v [(size_t)MM * HH];        // 64 MB
__device__ float g_A [CNK * NSEQ];
__device__ float g_Bc[CNK * NSEQ];
__device__ float g_P [CNK * NSEQ];

// ---------------- helpers ----------------
__device__ __forceinline__ float tf32r(float x) {
    uint32_t u;
    asm("cvt.rna.tf32.f32 %0, %1;" : "=r"(u) : "f"(x));
    return __uint_as_float(u);
}

#define CP_ASYNC16(dst, src) \
    asm volatile("cp.async.cg.shared.global [%0], [%1], 16;" :: "r"(dst), "l"(src))
#define CP_COMMIT() asm volatile("cp.async.commit_group;" ::: "memory")
#define CP_WAIT0()  asm volatile("cp.async.wait_group 0;" ::: "memory")

#define MMA_TF32(d, a, b) \
    asm volatile("mma.sync.aligned.m16n8k8.row.col.f32.tf32.tf32.f32 " \
        "{%0,%1,%2,%3}, {%4,%5,%6,%7}, {%8,%9}, {%0,%1,%2,%3};" \
        : "+f"((d)[0]), "+f"((d)[1]), "+f"((d)[2]), "+f"((d)[3]) \
        : "r"(__float_as_uint((a)[0])), "r"(__float_as_uint((a)[1])), \
          "r"(__float_as_uint((a)[2])), "r"(__float_as_uint((a)[3])), \
          "r"(__float_as_uint((b)[0])), "r"(__float_as_uint((b)[1])))

// ---------------- 1. LayerNorm (outputs tf32-rounded) ----------------
__global__ void __launch_bounds__(128) ln_kernel(const float* __restrict__ x,
                                                 const float* __restrict__ gamma,
                                                 const float* __restrict__ beta) {
    const int row = blockIdx.x;
    const int tid = threadIdx.x;
    const float4* xr = (const float4*)(x + (size_t)row * DD);
    float4 v = xr[tid];
    float s  = v.x + v.y + v.z + v.w;
    float ss = v.x*v.x + v.y*v.y + v.z*v.z + v.w*v.w;
    #pragma unroll
    for (int o = 16; o; o >>= 1) {
        s  += __shfl_xor_sync(0xffffffffu, s,  o);
        ss += __shfl_xor_sync(0xffffffffu, ss, o);
    }
    __shared__ float sh[8];
    const int w = tid >> 5, l = tid & 31;
    if (l == 0) { sh[w] = s; sh[4 + w] = ss; }
    __syncthreads();
    if (tid == 0) {
        float S  = sh[0] + sh[1] + sh[2] + sh[3];
        float SS = sh[4] + sh[5] + sh[6] + sh[7];
        float mu  = S * (1.0f / DD);
        float var = SS * (1.0f / DD) - mu * mu;
        sh[0] = mu;
        sh[1] = rsqrtf(var + 1e-10f);
    }
    __syncthreads();
    const float mu = sh[0], rs = sh[1];
    float4 g  = ((const float4*)gamma)[tid];
    float4 bb = ((const float4*)beta)[tid];
    float4 o;
    o.x = tf32r((v.x - mu) * rs * g.x + bb.x);
    o.y = tf32r((v.y - mu) * rs * g.y + bb.y);
    o.z = tf32r((v.z - mu) * rs * g.z + bb.z);
    o.w = tf32r((v.w - mu) * rs * g.w + bb.w);
    ((float4*)(g_xn + (size_t)row * DD))[tid] = o;
}

// ---------------- 1b. W transpose+interleave: g_Wt[2h+g][k] = W[k][g*HH+h] -----
__global__ void __launch_bounds__(256) wt_kernel(const float* __restrict__ W) {
    const int idx = blockIdx.x * 256 + threadIdx.x;   // < NN*KK
    const int np = idx >> 9;        // 0..1023
    const int k  = idx & 511;
    const int h  = np >> 1;
    const int gs = np & 1;
    g_Wt[idx] = tf32r(W[(size_t)k * NN + gs * HH + h]);
}

// ---------------- 2. mma.sync tf32 GEMM + fused activation epilogue ------------
#define BM 128
#define BN 128
#define BK 32
#define NSTG (KK / BK)          // 16
#define PAD  36                  // floats per smem row (bank-conflict-free)
#define ATILE (BM * PAD)         // 4608 floats
#define SMEM_FLOATS (4 * ATILE)  // A0 A1 B0 B1 = 73728 bytes

__device__ __forceinline__ void load_stage(const float* __restrict__ Ag,
                                           const float* __restrict__ Bg,
                                           uint32_t sA, uint32_t sB,
                                           int k0, int tid) {
    #pragma unroll
    for (int i = 0; i < 4; i++) {                 // A: 128x32 fp32 = 1024 float4
        int q = tid + i * 256;
        int m = q >> 3, k4 = q & 7;
        CP_ASYNC16(sA + m * (PAD * 4) + k4 * 16,
                   Ag + (size_t)m * KK + k0 + k4 * 4);
    }
    #pragma unroll
    for (int i = 0; i < 4; i++) {                 // B: 128x32
        int q = tid + i * 256;
        int n = q >> 3, k4 = q & 7;
        CP_ASYNC16(sB + n * (PAD * 4) + k4 * 16,
                   Bg + (size_t)n * KK + k0 + k4 * 4);
    }
}

__global__ void __launch_bounds__(256) gemm_kernel() {
    extern __shared__ float sm[];
    const int tid  = threadIdx.x;
    const int lane = tid & 31;
    const int wid  = tid >> 5;          // 8 warps: 2 (M) x 4 (N)
    const int wm   = wid & 1;
    const int wn   = wid >> 1;
    const int rowBase = blockIdx.y * BM;
    const int colBase = blockIdx.x * BN;

    const float* Ag = g_xn + (size_t)rowBase * KK;
    const float* Bg = g_Wt + (size_t)colBase * KK;

    uint32_t sbase = (uint32_t)__cvta_generic_to_shared(sm);
    uint32_t sA[2] = { sbase,                sbase + ATILE * 4 };
    uint32_t sB[2] = { sbase + 2*ATILE*4,    sbase + 3*ATILE*4 };
    const float* Abuf[2] = { sm,            sm + ATILE };
    const float* Bbuf[2] = { sm + 2*ATILE,  sm + 3*ATILE };

    float acc[4][4][4];
    #pragma unroll
    for (int i = 0; i < 4; i++)
        #pragma unroll
        for (int j = 0; j < 4; j++)
            #pragma unroll
            for (int q = 0; q < 4; q++) acc[i][j][q] = 0.0f;

    load_stage(Ag, Bg, sA[0], sB[0], 0, tid);
    CP_COMMIT();

    for (int s = 0; s < NSTG; s++) {
        CP_WAIT0();
        __syncthreads();
        if (s + 1 < NSTG) {
            load_stage(Ag, Bg, sA[(s+1)&1], sB[(s+1)&1], (s + 1) * BK, tid);
            CP_COMMIT();
        }
        const float* Ab = Abuf[s & 1];
        const float* Bb = Bbuf[s & 1];
        #pragma unroll
        for (int k8 = 0; k8 < 4; k8++) {
            const int kc = k8 * 8 + (lane & 3);
            float a[4][4], b[4][2];
            #pragma unroll
            for (int mi = 0; mi < 4; mi++) {
                const int r = wm * 64 + mi * 16 + (lane >> 2);
                a[mi][0] = Ab[r * PAD + kc];
                a[mi][1] = Ab[(r + 8) * PAD + kc];
                a[mi][2] = Ab[r * PAD + kc + 4];
                a[mi][3] = Ab[(r + 8) * PAD + kc + 4];
            }
            #pragma unroll
            for (int ni = 0; ni < 4; ni++) {
                const int n = wn * 32 + ni * 8 + (lane >> 2);
                b[ni][0] = Bb[n * PAD + kc];
                b[ni][1] = Bb[n * PAD + kc + 4];
            }
            #pragma unroll
            for (int mi = 0; mi < 4; mi++)
                #pragma unroll
                for (int ni = 0; ni < 4; ni++)
                    MMA_TF32(acc[mi][ni], a[mi], b[ni]);
        }
        __syncthreads();
    }

    // Epilogue: acc pairs (c0,c1)/(c2,c3) are (k_gate, h_pre) of one h channel
    const int hBase = (colBase >> 1) + wn * 16;
    const int mWarp = rowBase + wm * 64;
    #pragma unroll
    for (int mi = 0; mi < 4; mi++) {
        #pragma unroll
        for (int ni = 0; ni < 4; ni++) {
            const int h = hBase + ni * 4 + (lane & 3);
            const int m0 = mWarp + mi * 16 + (lane >> 2);
            #pragma unroll
            for (int rr = 0; rr < 2; rr++) {
                float k  = acc[mi][ni][2 * rr];
                float hp = acc[mi][ni][2 * rr + 1];
                k = fminf(fmaxf(k, -30.0f), 30.0f);
                float ek = __expf(k);
                float c  = 1.0f / (1.0f + ek);       // sigmoid(-k)
                float z  = ek * c;                    // sigmoid(k)
                float g  = (hp >= 0.0f) ? (hp + 0.5f)
                                        : (1.0f / (1.0f + __expf(-hp)));
                const size_t off = (size_t)(m0 + rr * 8) * HH + h;
                g_c[off] = c;
                g_v[off] = z * g;
            }
        }
    }
}

// ---------------- 4. Scan phase 1 ----------------
__global__ void __launch_bounds__(256) scan1_kernel() {
    const int idx = blockIdx.x * 256 + threadIdx.x;
    const int h  = idx & 511;
    const int ci = (idx >> 9) & (CNK - 1);
    const int b  = idx >> 15;
    const int seq = b * HH + h;
    size_t off = ((size_t)(b * TT + ci * CL)) * HH + h;
    float A = 1.0f, Bv = 0.0f;
    #pragma unroll 4
    for (int l = 0; l < CL; l++) {
        float c = g_c[off], v = g_v[off];
        A *= c;
        Bv = fmaf(c, Bv, v);
        off += HH;
    }
    g_A [ci * NSEQ + seq] = A;
    g_Bc[ci * NSEQ + seq] = Bv;
}

// ---------------- 5. Scan phase 2 ----------------
__global__ void __launch_bounds__(256) scan2_kernel(float* __restrict__ hidden) {
    const int seq = blockIdx.x * 256 + threadIdx.x;
    float p = 0.0f;
    #pragma unroll 8
    for (int ci = 0; ci < CNK; ci++) {
        g_P[ci * NSEQ + seq] = p;
        p = fmaf(g_A[ci * NSEQ + seq], p, g_Bc[ci * NSEQ + seq]);
    }
    hidden[seq] = p;
}

// ---------------- 6. Scan phase 3 ----------------
__global__ void __launch_bounds__(256) scan3_kernel(const float* __restrict__ x,
                                                    float* __restrict__ out) {
    const int idx = blockIdx.x * 256 + threadIdx.x;
    const int h  = idx & 511;
    const int ci = (idx >> 9) & (CNK - 1);
    const int b  = idx >> 15;
    const int seq = b * HH + h;
    float hs = g_P[ci * NSEQ + seq];
    size_t off = ((size_t)(b * TT + ci * CL)) * HH + h;
    #pragma unroll 4
    for (int l = 0; l < CL; l++) {
        float c = g_c[off], v = g_v[off];
        hs = fmaf(c, hs, v);
        out[off] = hs + x[off];
        off += HH;
    }
}

// ---------------- launch ----------------
extern "C" void kernel_launch(void* const* d_in, const int* in_sizes, int n_in,
                              void* d_out, int out_size) {
    const float* x     = (const float*)d_in[0];
    const float* gamma = (const float*)d_in[1];
    const float* beta  = (const float*)d_in[2];
    const float* W     = (const float*)d_in[3];
    float* out    = (float*)d_out;
    float* hidden = out + (size_t)MM * DD;

    cudaFuncSetAttribute(gemm_kernel, cudaFuncAttributeMaxDynamicSharedMemorySize,
                         SMEM_FLOATS * 4);

    ln_kernel  <<<MM, 128>>>(x, gamma, beta);
    wt_kernel  <<<(NN * KK) / 256, 256>>>(W);
    gemm_kernel<<<dim3(NN / BN, MM / BM), 256, SMEM_FLOATS * 4>>>();
    scan1_kernel<<<(NSEQ * CNK) / 256, 256>>>();
    scan2_kernel<<<NSEQ / 256, 256>>>(hidden);
    scan3_kernel<<<(NSEQ * CNK) / 256, 256>>>(x, out);
}

// round 6
// speedup vs baseline: 3.5042x; 1.4177x over previous
#include <cuda_runtime.h>
#include <cuda_fp16.h>
#include <math.h>
#include <stdint.h>

// Problem dims (fixed)
#define BB   8
#define TT   4096
#define DD   512
#define HH   512
#define MM   (BB*TT)          // 32768 rows
#define NN   (2*HH)           // 1024 gemm cols
#define KK   DD               // 512

// Chunked scan config
#define CNK  64
#define CL   (TT/CNK)         // 64
#define NSEQ (BB*HH)          // 4096

// ---------------- scratch ----------------
__device__ __align__(16) __half g_xn[(size_t)MM * DD];   // 32 MB  layernormed x (fp16)
__device__ __align__(16) __half g_Wt[(size_t)NN * KK];   // 1 MB   W transposed+interleaved (fp16)
__device__ float g_c [(size_t)MM * HH];                  // 64 MB
__device__ float g_v [(size_t)MM * HH];                  // 64 MB
__device__ float g_A [CNK * NSEQ];
__device__ float g_Bc[CNK * NSEQ];
__device__ float g_P [CNK * NSEQ];

// ---------------- helpers ----------------
#define CP_ASYNC16(dst, src) \
    asm volatile("cp.async.cg.shared.global [%0], [%1], 16;" :: "r"(dst), "l"(src))
#define CP_COMMIT() asm volatile("cp.async.commit_group;" ::: "memory")
#define CP_WAIT0()  asm volatile("cp.async.wait_group 0;" ::: "memory")

#define MMA_F16(d, a, b) \
    asm volatile("mma.sync.aligned.m16n8k16.row.col.f32.f16.f16.f32 " \
        "{%0,%1,%2,%3}, {%4,%5,%6,%7}, {%8,%9}, {%0,%1,%2,%3};" \
        : "+f"((d)[0]), "+f"((d)[1]), "+f"((d)[2]), "+f"((d)[3]) \
        : "r"((a)[0]), "r"((a)[1]), "r"((a)[2]), "r"((a)[3]), \
          "r"((b)[0]), "r"((b)[1]))

// ---------------- 1. LayerNorm (outputs fp16) ----------------
__global__ void __launch_bounds__(128) ln_kernel(const float* __restrict__ x,
                                                 const float* __restrict__ gamma,
                                                 const float* __restrict__ beta) {
    const int row = blockIdx.x;
    const int tid = threadIdx.x;
    const float4* xr = (const float4*)(x + (size_t)row * DD);
    float4 v = xr[tid];
    float s  = v.x + v.y + v.z + v.w;
    float ss = v.x*v.x + v.y*v.y + v.z*v.z + v.w*v.w;
    #pragma unroll
    for (int o = 16; o; o >>= 1) {
        s  += __shfl_xor_sync(0xffffffffu, s,  o);
        ss += __shfl_xor_sync(0xffffffffu, ss, o);
    }
    __shared__ float sh[8];
    const int w = tid >> 5, l = tid & 31;
    if (l == 0) { sh[w] = s; sh[4 + w] = ss; }
    __syncthreads();
    if (tid == 0) {
        float S  = sh[0] + sh[1] + sh[2] + sh[3];
        float SS = sh[4] + sh[5] + sh[6] + sh[7];
        float mu  = S * (1.0f / DD);
        float var = SS * (1.0f / DD) - mu * mu;
        sh[0] = mu;
        sh[1] = rsqrtf(var + 1e-10f);
    }
    __syncthreads();
    const float mu = sh[0], rs = sh[1];
    float4 g  = ((const float4*)gamma)[tid];
    float4 bb = ((const float4*)beta)[tid];
    __half2 o01 = __floats2half2_rn((v.x - mu) * rs * g.x + bb.x,
                                    (v.y - mu) * rs * g.y + bb.y);
    __half2 o23 = __floats2half2_rn((v.z - mu) * rs * g.z + bb.z,
                                    (v.w - mu) * rs * g.w + bb.w);
    __half2* dst = (__half2*)(g_xn + (size_t)row * DD);
    dst[2 * tid]     = o01;
    dst[2 * tid + 1] = o23;
}

// ---------------- 1b. W transpose+interleave: g_Wt[2h+g][k] = W[k][g*HH+h] -----
__global__ void __launch_bounds__(256) wt_kernel(const float* __restrict__ W) {
    const int idx = blockIdx.x * 256 + threadIdx.x;   // < NN*KK
    const int np = idx >> 9;        // 0..1023
    const int k  = idx & 511;
    const int h  = np >> 1;
    const int gs = np & 1;
    g_Wt[idx] = __float2half_rn(W[(size_t)k * NN + gs * HH + h]);
}

// ---------------- 2. mma.sync fp16 GEMM + fused activation epilogue ------------
#define BM 128
#define BN 128
#define BK 64
#define NSTG (KK / BK)           // 8
#define ROWB 144                  // bytes per smem row (72 halves) - conflict-free
#define TILEB (BM * ROWB)         // 18432 bytes per tile
#define SMEM_BYTES (4 * TILEB)    // A0 A1 B0 B1 = 73728 bytes

__device__ __forceinline__ void load_stage(const __half* __restrict__ Ag,
                                           const __half* __restrict__ Bg,
                                           uint32_t sA, uint32_t sB,
                                           int k0, int tid) {
    #pragma unroll
    for (int i = 0; i < 4; i++) {                 // A: 128 rows x 64 halves
        int q = tid + i * 256;
        int m = q >> 3, k8 = q & 7;
        CP_ASYNC16(sA + m * ROWB + k8 * 16,
                   Ag + (size_t)m * KK + k0 + k8 * 8);
    }
    #pragma unroll
    for (int i = 0; i < 4; i++) {                 // B: 128 rows x 64 halves
        int q = tid + i * 256;
        int n = q >> 3, k8 = q & 7;
        CP_ASYNC16(sB + n * ROWB + k8 * 16,
                   Bg + (size_t)n * KK + k0 + k8 * 8);
    }
}

__global__ void __launch_bounds__(256) gemm_kernel() {
    extern __shared__ char sm[];
    const int tid  = threadIdx.x;
    const int lane = tid & 31;
    const int grp  = lane >> 2;         // 0..7
    const int q4   = lane & 3;          // 0..3
    const int wid  = tid >> 5;          // 8 warps: 2 (M) x 4 (N)
    const int wm   = wid & 1;
    const int wn   = wid >> 1;
    const int rowBase = blockIdx.y * BM;
    const int colBase = blockIdx.x * BN;

    const __half* Ag = g_xn + (size_t)rowBase * KK;
    const __half* Bg = g_Wt + (size_t)colBase * KK;

    uint32_t sbase = (uint32_t)__cvta_generic_to_shared(sm);
    uint32_t sA[2] = { sbase,             sbase + TILEB };
    uint32_t sB[2] = { sbase + 2*TILEB,   sbase + 3*TILEB };
    const char* Abuf[2] = { sm,            sm + TILEB };
    const char* Bbuf[2] = { sm + 2*TILEB,  sm + 3*TILEB };

    float acc[4][4][4];
    #pragma unroll
    for (int i = 0; i < 4; i++)
        #pragma unroll
        for (int j = 0; j < 4; j++)
            #pragma unroll
            for (int p = 0; p < 4; p++) acc[i][j][p] = 0.0f;

    load_stage(Ag, Bg, sA[0], sB[0], 0, tid);
    CP_COMMIT();

    for (int s = 0; s < NSTG; s++) {
        CP_WAIT0();
        __syncthreads();
        if (s + 1 < NSTG) {
            load_stage(Ag, Bg, sA[(s+1)&1], sB[(s+1)&1], (s + 1) * BK, tid);
            CP_COMMIT();
        }
        const char* Ab = Abuf[s & 1];
        const char* Bb = Bbuf[s & 1];
        #pragma unroll
        for (int k16 = 0; k16 < 4; k16++) {
            const int kb = k16 * 32 + q4 * 4;   // byte offset of this lane's k pair
            uint32_t a[4][4], b[4][2];
            #pragma unroll
            for (int mi = 0; mi < 4; mi++) {
                const int r = wm * 64 + mi * 16 + grp;
                a[mi][0] = *(const uint32_t*)(Ab + r * ROWB + kb);
                a[mi][1] = *(const uint32_t*)(Ab + (r + 8) * ROWB + kb);
                a[mi][2] = *(const uint32_t*)(Ab + r * ROWB + kb + 16);
                a[mi][3] = *(const uint32_t*)(Ab + (r + 8) * ROWB + kb + 16);
            }
            #pragma unroll
            for (int ni = 0; ni < 4; ni++) {
                const int n = wn * 32 + ni * 8 + grp;
                b[ni][0] = *(const uint32_t*)(Bb + n * ROWB + kb);
                b[ni][1] = *(const uint32_t*)(Bb + n * ROWB + kb + 16);
            }
            #pragma unroll
            for (int mi = 0; mi < 4; mi++)
                #pragma unroll
                for (int ni = 0; ni < 4; ni++)
                    MMA_F16(acc[mi][ni], a[mi], b[ni]);
        }
        __syncthreads();
    }

    // Epilogue: acc pairs (c0,c1)/(c2,c3) are (k_gate, h_pre) of one h channel
    const int hBase = (colBase >> 1) + wn * 16;
    const int mWarp = rowBase + wm * 64;
    #pragma unroll
    for (int mi = 0; mi < 4; mi++) {
        #pragma unroll
        for (int ni = 0; ni < 4; ni++) {
            const int h = hBase + ni * 4 + q4;
            const int m0 = mWarp + mi * 16 + grp;
            #pragma unroll
            for (int rr = 0; rr < 2; rr++) {
                float k  = acc[mi][ni][2 * rr];
                float hp = acc[mi][ni][2 * rr + 1];
                k = fminf(fmaxf(k, -30.0f), 30.0f);
                float ek = __expf(k);
                float c  = 1.0f / (1.0f + ek);       // sigmoid(-k)
                float z  = ek * c;                    // sigmoid(k)
                float g  = (hp >= 0.0f) ? (hp + 0.5f)
                                        : (1.0f / (1.0f + __expf(-hp)));
                const size_t off = (size_t)(m0 + rr * 8) * HH + h;
                g_c[off] = c;
                g_v[off] = z * g;
            }
        }
    }
}

// ---------------- 4. Scan phase 1 ----------------
__global__ void __launch_bounds__(256) scan1_kernel() {
    const int idx = blockIdx.x * 256 + threadIdx.x;
    const int h  = idx & 511;
    const int ci = (idx >> 9) & (CNK - 1);
    const int b  = idx >> 15;
    const int seq = b * HH + h;
    size_t off = ((size_t)(b * TT + ci * CL)) * HH + h;
    float A = 1.0f, Bv = 0.0f;
    #pragma unroll 4
    for (int l = 0; l < CL; l++) {
        float c = g_c[off], v = g_v[off];
        A *= c;
        Bv = fmaf(c, Bv, v);
        off += HH;
    }
    g_A [ci * NSEQ + seq] = A;
    g_Bc[ci * NSEQ + seq] = Bv;
}

// ---------------- 5. Scan phase 2 ----------------
__global__ void __launch_bounds__(256) scan2_kernel(float* __restrict__ hidden) {
    const int seq = blockIdx.x * 256 + threadIdx.x;
    float p = 0.0f;
    #pragma unroll 8
    for (int ci = 0; ci < CNK; ci++) {
        g_P[ci * NSEQ + seq] = p;
        p = fmaf(g_A[ci * NSEQ + seq], p, g_Bc[ci * NSEQ + seq]);
    }
    hidden[seq] = p;
}

// ---------------- 6. Scan phase 3 ----------------
__global__ void __launch_bounds__(256) scan3_kernel(const float* __restrict__ x,
                                                    float* __restrict__ out) {
    const int idx = blockIdx.x * 256 + threadIdx.x;
    const int h  = idx & 511;
    const int ci = (idx >> 9) & (CNK - 1);
    const int b  = idx >> 15;
    const int seq = b * HH + h;
    float hs = g_P[ci * NSEQ + seq];
    size_t off = ((size_t)(b * TT + ci * CL)) * HH + h;
    #pragma unroll 4
    for (int l = 0; l < CL; l++) {
        float c = g_c[off], v = g_v[off];
        hs = fmaf(c, hs, v);
        out[off] = hs + x[off];
        off += HH;
    }
}

// ---------------- launch ----------------
extern "C" void kernel_launch(void* const* d_in, const int* in_sizes, int n_in,
                              void* d_out, int out_size) {
    const float* x     = (const float*)d_in[0];
    const float* gamma = (const float*)d_in[1];
    const float* beta  = (const float*)d_in[2];
    const float* W     = (const float*)d_in[3];
    float* out    = (float*)d_out;
    float* hidden = out + (size_t)MM * DD;

    cudaFuncSetAttribute(gemm_kernel, cudaFuncAttributeMaxDynamicSharedMemorySize,
                         SMEM_BYTES);

    ln_kernel  <<<MM, 128>>>(x, gamma, beta);
    wt_kernel  <<<(NN * KK) / 256, 256>>>(W);
    gemm_kernel<<<dim3(NN / BN, MM / BM), 256, SMEM_BYTES>>>();
    scan1_kernel<<<(NSEQ * CNK) / 256, 256>>>();
    scan2_kernel<<<NSEQ / 256, 256>>>(hidden);
    scan3_kernel<<<(NSEQ * CNK) / 256, 256>>>(x, out);
}